// round 6
// baseline (speedup 1.0000x reference)
#include <cuda_runtime.h>
#include <cuda_bf16.h>

// ChannelSelfAttention: B=4,H=512,W=256, C=2.
// s(w,u) = c0(w)*xa[u] + c1(w)*xb[u] + c2(w); A=Σe*xa, B=Σe*xb, D=Σe.
// MUFU is the binding pipe -> route 3/16 of the exp2s to an fma-pipe
// polynomial path (magic-round + deg-4 Horner + IMAD exponent splice).

#define WIDTH 256

typedef unsigned long long u64;
typedef unsigned int u32;

__device__ __forceinline__ u64 f2_pack(float lo, float hi) {
    u64 r; asm("mov.b64 %0, {%1,%2};" : "=l"(r) : "f"(lo), "f"(hi)); return r;
}
__device__ __forceinline__ void f2_unpack(u64 v, float& lo, float& hi) {
    asm("mov.b64 {%0,%1}, %2;" : "=f"(lo), "=f"(hi) : "l"(v));
}
__device__ __forceinline__ void f2_unpack_u(u64 v, u32& lo, u32& hi) {
    asm("mov.b64 {%0,%1}, %2;" : "=r"(lo), "=r"(hi) : "l"(v));
}
__device__ __forceinline__ u64 f2_pack_u(u32 lo, u32 hi) {
    u64 r; asm("mov.b64 %0, {%1,%2};" : "=l"(r) : "r"(lo), "r"(hi)); return r;
}
__device__ __forceinline__ u64 f2_fma(u64 a, u64 b, u64 c) {
    u64 r; asm("fma.rn.f32x2 %0, %1, %2, %3;" : "=l"(r) : "l"(a), "l"(b), "l"(c)); return r;
}
__device__ __forceinline__ u64 f2_add(u64 a, u64 b) {
    u64 r; asm("add.rn.f32x2 %0, %1, %2;" : "=l"(r) : "l"(a), "l"(b)); return r;
}
__device__ __forceinline__ float fast_ex2(float s) {
    float e; asm("ex2.approx.ftz.f32 %0, %1;" : "=f"(e) : "f"(s)); return e;
}

// packed poly constants (built per-thread; cheap, hoisted out of the loop)
struct PolyK {
    u64 magic, negmagic, neg1, C1, C2, C3, C4;
};

// exp2 on a packed f32x2 pair, fma-pipe only. Valid for |s| < ~120.
__device__ __forceinline__ u64 exp2_poly_f2(u64 s, const PolyK& K) {
    u64 r = f2_add(s, K.magic);          // round(s) in low mantissa bits
    u64 t = f2_add(r, K.negmagic);       // t = round(s) as float
    u64 f = f2_fma(t, K.neg1, s);        // f = s - t, f in [-0.5, 0.5]
    // p = 1 + f*(ln2 + f*(ln2^2/2 + f*(ln2^3/6 + f*ln2^4/24)))
    u64 p = f2_fma(f, K.C4, K.C3);
    p = f2_fma(f, p, K.C2);
    p = f2_fma(f, p, K.C1);
    p = f2_fma(f, p, f2_pack(1.0f, 1.0f) /*folded below*/);
    u32 r0, r1, p0, p1;
    f2_unpack_u(r, r0, r1);
    f2_unpack_u(p, p0, p1);
    // splice integer part into exponent: bits(r)-0x4B400000 = i, and
    // 0x4B400000*2^23 ≡ 0 mod 2^32, so IMAD alone is exact.
    u32 o0 = r0 * 8388608u + p0;         // + (i << 23)
    u32 o1 = r1 * 8388608u + p1;
    return f2_pack_u(o0, o1);
}

__device__ __forceinline__ u64 exp2_mufu_f2(u64 s) {
    float s0, s1;
    f2_unpack(s, s0, s1);
    return f2_pack(fast_ex2(s0), fast_ex2(s1));
}

__global__ __launch_bounds__(WIDTH) void channel_attn_kernel(
    const float* __restrict__ x1, const float* __restrict__ x2,
    const float* __restrict__ wq, const float* __restrict__ bq,
    const float* __restrict__ wk, const float* __restrict__ bk,
    const float* __restrict__ wv, const float* __restrict__ bv,
    float* __restrict__ out, int n_elem)
{
    __shared__ __align__(16) float sha[WIDTH];
    __shared__ __align__(16) float shb[WIDTH];

    const int row  = blockIdx.x;
    const int w    = threadIdx.x;
    const int base = row * WIDTH;

    const float xa = x1[base + w];
    const float xb = x2[base + w];
    sha[w] = xa;
    shb[w] = xb;

    const float q00 = __ldg(&wq[0]), q01 = __ldg(&wq[1]);
    const float q10 = __ldg(&wq[2]), q11 = __ldg(&wq[3]);
    const float k00 = __ldg(&wk[0]), k01 = __ldg(&wk[1]);
    const float k10 = __ldg(&wk[2]), k11 = __ldg(&wk[3]);
    const float v00 = __ldg(&wv[0]), v01 = __ldg(&wv[1]);
    const float v10 = __ldg(&wv[2]), v11 = __ldg(&wv[3]);
    const float bq0 = __ldg(&bq[0]), bq1 = __ldg(&bq[1]);
    const float bk0 = __ldg(&bk[0]), bk1 = __ldg(&bk[1]);
    const float bv0 = __ldg(&bv[0]), bv1 = __ldg(&bv[1]);

    const float LOG2E = 1.4426950408889634f;
    const float a0 = fmaf(q00, xa, fmaf(q01, xb, bq0)) * LOG2E;
    const float a1 = fmaf(q10, xa, fmaf(q11, xb, bq1)) * LOG2E;
    const float c0 = fmaf(a0, k00, a1 * k10);
    const float c1 = fmaf(a0, k01, a1 * k11);
    const float c2 = fmaf(a0, bk0, a1 * bk1);

    const u64 c0p = f2_pack(c0, c0);
    const u64 c1p = f2_pack(c1, c1);
    const u64 c2p = f2_pack(c2, c2);

    PolyK K;
    K.magic    = f2_pack(12582912.0f, 12582912.0f);    // 1.5 * 2^23
    K.negmagic = f2_pack(-12582912.0f, -12582912.0f);
    K.neg1     = f2_pack(-1.0f, -1.0f);
    K.C1       = f2_pack(0.6931471806f, 0.6931471806f);
    K.C2       = f2_pack(0.2402265070f, 0.2402265070f);
    K.C3       = f2_pack(0.0555041087f, 0.0555041087f);
    K.C4       = f2_pack(0.0096181291f, 0.0096181291f);

    const unsigned sa_base = (unsigned)__cvta_generic_to_shared(sha);
    const unsigned sb_base = (unsigned)__cvta_generic_to_shared(shb);

    __syncthreads();

    u64 Dx = 0ull, Dy = 0ull;
    u64 Ax = 0ull, Ay = 0ull;
    u64 Bx = 0ull, By = 0ull;

    // outer rolled (keeps body L0-resident), inner fully unrolled: 32 u / macro
#pragma unroll 1
    for (int u0 = 0; u0 < WIDTH; u0 += 32) {
#pragma unroll
        for (int c = 0; c < 8; ++c) {        // 4 u per chunk, pairs (2c, 2c+1)
            const int off = (u0 + 4 * c) * 4;
            u64 xa01, xa23, xb01, xb23;
            asm("ld.shared.v2.b64 {%0,%1}, [%2];"
                : "=l"(xa01), "=l"(xa23) : "r"(sa_base + off));
            asm("ld.shared.v2.b64 {%0,%1}, [%2];"
                : "=l"(xb01), "=l"(xb23) : "r"(sb_base + off));

            const u64 s01 = f2_fma(c0p, xa01, f2_fma(c1p, xb01, c2p));
            const u64 s23 = f2_fma(c0p, xa23, f2_fma(c1p, xb23, c2p));

            // poly path for pair indices {5, 10, 15} of 16 (f = 3/16)
            const bool poly01 = (2 * c == 10);              // pair idx 2c
            const bool poly23 = (2 * c + 1 == 5) || (2 * c + 1 == 15);

            const u64 e01 = poly01 ? exp2_poly_f2(s01, K) : exp2_mufu_f2(s01);
            const u64 e23 = poly23 ? exp2_poly_f2(s23, K) : exp2_mufu_f2(s23);

            Dx = f2_add(Dx, e01);
            Dy = f2_add(Dy, e23);
            Ax = f2_fma(e01, xa01, Ax);
            Ay = f2_fma(e23, xa23, Ay);
            Bx = f2_fma(e01, xb01, Bx);
            By = f2_fma(e23, xb23, By);
        }
    }

    float d0, d1, a0f, a1f, b0f, b1f;
    f2_unpack(f2_add(Dx, Dy), d0, d1);
    f2_unpack(f2_add(Ax, Ay), a0f, a1f);
    f2_unpack(f2_add(Bx, By), b0f, b1f);
    const float Dv = d0 + d1;
    const float Av = a0f + a1f;
    const float Bv = b0f + b1f;

    const float inv = 1.0f / Dv;
    const float n0  = fmaf(v00, Av, fmaf(v01, Bv, bv0 * Dv));
    const float n1  = fmaf(v10, Av, fmaf(v11, Bv, bv1 * Dv));

    out[base + w]          = fmaf(n0, inv, xa);
    out[n_elem + base + w] = fmaf(n1, inv, xb);
}

extern "C" void kernel_launch(void* const* d_in, const int* in_sizes, int n_in,
                              void* d_out, int out_size)
{
    const float* x1 = (const float*)d_in[0];
    const float* x2 = (const float*)d_in[1];
    const float* wq = (const float*)d_in[2];
    const float* bq = (const float*)d_in[3];
    const float* wk = (const float*)d_in[4];
    const float* bk = (const float*)d_in[5];
    const float* wv = (const float*)d_in[6];
    const float* bv = (const float*)d_in[7];
    float* out = (float*)d_out;

    const int n_elem = in_sizes[0];        // B*H*W = 524288
    const int rows   = n_elem / WIDTH;     // B*H   = 2048

    channel_attn_kernel<<<rows, WIDTH>>>(x1, x2, wq, bq, wk, bk, wv, bv,
                                         out, n_elem);
}

// round 9
// speedup vs baseline: 1.0219x; 1.0219x over previous
#include <cuda_runtime.h>
#include <cuda_bf16.h>

// ChannelSelfAttention: B=4,H=512,W=256, C=2.
// s(w,u) = c0(w)*xa[u] + c1(w)*xb[u]  (c2 dropped: softmax shift-invariant)
// A=Σe*xa, B=Σe*xb, D=Σe; V applied once per thread at the end.
// 3/16 of exp2s routed to an fma-pipe polynomial; rest on MUFU.
// Reg-lean: single acc stream, minimal poly constants, launch_bounds cap.

#define WIDTH 256

typedef unsigned long long u64;
typedef unsigned int u32;

__device__ __forceinline__ u64 f2_pack(float lo, float hi) {
    u64 r; asm("mov.b64 %0, {%1,%2};" : "=l"(r) : "f"(lo), "f"(hi)); return r;
}
__device__ __forceinline__ void f2_unpack(u64 v, float& lo, float& hi) {
    asm("mov.b64 {%0,%1}, %2;" : "=f"(lo), "=f"(hi) : "l"(v));
}
__device__ __forceinline__ void f2_unpack_u(u64 v, u32& lo, u32& hi) {
    asm("mov.b64 {%0,%1}, %2;" : "=r"(lo), "=r"(hi) : "l"(v));
}
__device__ __forceinline__ u64 f2_pack_u(u32 lo, u32 hi) {
    u64 r; asm("mov.b64 %0, {%1,%2};" : "=l"(r) : "r"(lo), "r"(hi)); return r;
}
__device__ __forceinline__ u64 f2_fma(u64 a, u64 b, u64 c) {
    u64 r; asm("fma.rn.f32x2 %0, %1, %2, %3;" : "=l"(r) : "l"(a), "l"(b), "l"(c)); return r;
}
__device__ __forceinline__ u64 f2_mul(u64 a, u64 b) {
    u64 r; asm("mul.rn.f32x2 %0, %1, %2;" : "=l"(r) : "l"(a), "l"(b)); return r;
}
__device__ __forceinline__ u64 f2_add(u64 a, u64 b) {
    u64 r; asm("add.rn.f32x2 %0, %1, %2;" : "=l"(r) : "l"(a), "l"(b)); return r;
}
__device__ __forceinline__ u64 f2_sub(u64 a, u64 b) {
    u64 r; asm("sub.rn.f32x2 %0, %1, %2;" : "=l"(r) : "l"(a), "l"(b)); return r;
}
__device__ __forceinline__ float fast_ex2(float s) {
    float e; asm("ex2.approx.ftz.f32 %0, %1;" : "=f"(e) : "f"(s)); return e;
}

// minimal poly constant set: 6 u64 = 12 regs
struct PolyK { u64 magic, one, C1, C2, C3, C4; };

// exp2 on a packed pair, fma-pipe. |s| < ~120.
__device__ __forceinline__ u64 exp2_poly_f2(u64 s, const PolyK& K) {
    u64 r = f2_add(s, K.magic);     // round(s) captured in mantissa
    u64 t = f2_sub(r, K.magic);     // t = round(s) as float
    u64 f = f2_sub(s, t);           // f in [-0.5, 0.5]
    u64 p = f2_fma(f, K.C4, K.C3);  // deg-4 Horner for exp2(f)
    p = f2_fma(f, p, K.C2);
    p = f2_fma(f, p, K.C1);
    p = f2_fma(f, p, K.one);
    u32 r0, r1, p0, p1;
    f2_unpack_u(r, r0, r1);
    f2_unpack_u(p, p0, p1);
    // exponent splice: bits(r)*2^23 == (i<<23) mod 2^32 (magic term vanishes)
    return f2_pack_u(r0 * 8388608u + p0, r1 * 8388608u + p1);
}

__device__ __forceinline__ u64 exp2_mufu_f2(u64 s) {
    float s0, s1;
    f2_unpack(s, s0, s1);
    return f2_pack(fast_ex2(s0), fast_ex2(s1));
}

__global__ __launch_bounds__(WIDTH, 5) void channel_attn_kernel(
    const float* __restrict__ x1, const float* __restrict__ x2,
    const float* __restrict__ wq, const float* __restrict__ bq,
    const float* __restrict__ wk, const float* __restrict__ bk,
    const float* __restrict__ wv, const float* __restrict__ bv,
    float* __restrict__ out, int n_elem)
{
    __shared__ __align__(16) float sha[WIDTH];
    __shared__ __align__(16) float shb[WIDTH];

    const int row  = blockIdx.x;
    const int w    = threadIdx.x;
    const int base = row * WIDTH;

    const float xa = x1[base + w];
    const float xb = x2[base + w];
    sha[w] = xa;
    shb[w] = xb;

    const float q00 = __ldg(&wq[0]), q01 = __ldg(&wq[1]);
    const float q10 = __ldg(&wq[2]), q11 = __ldg(&wq[3]);
    const float k00 = __ldg(&wk[0]), k01 = __ldg(&wk[1]);
    const float k10 = __ldg(&wk[2]), k11 = __ldg(&wk[3]);
    const float v00 = __ldg(&wv[0]), v01 = __ldg(&wv[1]);
    const float v10 = __ldg(&wv[2]), v11 = __ldg(&wv[3]);
    const float bq0 = __ldg(&bq[0]), bq1 = __ldg(&bq[1]);
    const float bv0 = __ldg(&bv[0]), bv1 = __ldg(&bv[1]);
    // bk only shifts the score by a per-thread constant -> cancels in softmax

    const float LOG2E = 1.4426950408889634f;
    const float a0 = fmaf(q00, xa, fmaf(q01, xb, bq0)) * LOG2E;
    const float a1 = fmaf(q10, xa, fmaf(q11, xb, bq1)) * LOG2E;
    const float c0 = fmaf(a0, k00, a1 * k10);
    const float c1 = fmaf(a0, k01, a1 * k11);

    const u64 c0p = f2_pack(c0, c0);
    const u64 c1p = f2_pack(c1, c1);

    PolyK K;
    K.magic = f2_pack(12582912.0f, 12582912.0f);   // 1.5 * 2^23
    K.one   = f2_pack(1.0f, 1.0f);
    K.C1    = f2_pack(0.6931471806f, 0.6931471806f);
    K.C2    = f2_pack(0.2402265070f, 0.2402265070f);
    K.C3    = f2_pack(0.0555041087f, 0.0555041087f);
    K.C4    = f2_pack(0.0096181291f, 0.0096181291f);

    const unsigned sa_base = (unsigned)__cvta_generic_to_shared(sha);
    const unsigned sb_base = (unsigned)__cvta_generic_to_shared(shb);

    __syncthreads();

    u64 D = 0ull, A = 0ull, B = 0ull;

#pragma unroll 1
    for (int u0 = 0; u0 < WIDTH; u0 += 32) {
#pragma unroll
        for (int c = 0; c < 8; ++c) {        // 4 u per chunk, pairs (2c, 2c+1)
            const int off = (u0 + 4 * c) * 4;
            u64 xa01, xa23, xb01, xb23;
            asm("ld.shared.v2.b64 {%0,%1}, [%2];"
                : "=l"(xa01), "=l"(xa23) : "r"(sa_base + off));
            asm("ld.shared.v2.b64 {%0,%1}, [%2];"
                : "=l"(xb01), "=l"(xb23) : "r"(sb_base + off));

            const u64 s01 = f2_fma(c0p, xa01, f2_mul(c1p, xb01));
            const u64 s23 = f2_fma(c0p, xa23, f2_mul(c1p, xb23));

            // poly on pair indices {2, 7, 12} of 16  (fraction 3/16)
            const bool poly01 = (2 * c == 2) || (2 * c == 12);
            const bool poly23 = (2 * c + 1 == 7);

            const u64 e01 = poly01 ? exp2_poly_f2(s01, K) : exp2_mufu_f2(s01);
            const u64 e23 = poly23 ? exp2_poly_f2(s23, K) : exp2_mufu_f2(s23);

            D = f2_add(D, f2_add(e01, e23));
            A = f2_fma(e01, xa01, f2_fma(e23, xa23, A));
            B = f2_fma(e01, xb01, f2_fma(e23, xb23, B));
        }
    }

    float d0, d1, a0f, a1f, b0f, b1f;
    f2_unpack(D, d0, d1);
    f2_unpack(A, a0f, a1f);
    f2_unpack(B, b0f, b1f);
    const float Dv = d0 + d1;
    const float Av = a0f + a1f;
    const float Bv = b0f + b1f;

    const float inv = 1.0f / Dv;
    const float n0  = fmaf(v00, Av, fmaf(v01, Bv, bv0 * Dv));
    const float n1  = fmaf(v10, Av, fmaf(v11, Bv, bv1 * Dv));

    out[base + w]          = fmaf(n0, inv, xa);
    out[n_elem + base + w] = fmaf(n1, inv, xb);
}

extern "C" void kernel_launch(void* const* d_in, const int* in_sizes, int n_in,
                              void* d_out, int out_size)
{
    const float* x1 = (const float*)d_in[0];
    const float* x2 = (const float*)d_in[1];
    const float* wq = (const float*)d_in[2];
    const float* bq = (const float*)d_in[3];
    const float* wk = (const float*)d_in[4];
    const float* bk = (const float*)d_in[5];
    const float* wv = (const float*)d_in[6];
    const float* bv = (const float*)d_in[7];
    float* out = (float*)d_out;

    const int n_elem = in_sizes[0];        // B*H*W = 524288
    const int rows   = n_elem / WIDTH;     // B*H   = 2048

    channel_attn_kernel<<<rows, WIDTH>>>(x1, x2, wq, bq, wk, bk, wv, bv,
                                         out, n_elem);
}